// round 1
// baseline (speedup 1.0000x reference)
#include <cuda_runtime.h>
#include <cstdint>
#include <cstddef>

// GCL (EGNN-style graph conv layer), factorized:
//   A = h @ We1_top, B = h @ We1_bot, C = h @ Wn1_top + bn1   (precompute)
//   t_e   = silu(A[row_e] + B[col_e] + be1)                    (edge gather)
//   mij_e = silu(t_e @ We2 + be2)                              (edge GEMM, written out + scatter-add)
//   agg_n = (sum_{e: row_e==n} mij_e) / 100
//   h_out = h + silu(C + agg @ Wn1_bot) @ Wn2 + bn2            (node GEMM x2)
// Output layout: [h_out (N*D) | mij (E*D)] fp32.

#define DD   128
#define PAD  132          // padded shared row (floats), keeps 16B alignment, kills LDS conflicts
#define TM   128          // tile rows (edges/nodes) per block
#define NTHR 256
#define MAXN 50048
#define MAXE 800128

__device__ float g_A[(size_t)MAXN * DD];
__device__ float g_B[(size_t)MAXN * DD];
__device__ float g_C[(size_t)MAXN * DD];
__device__ float g_agg[(size_t)MAXN * DD];
__device__ int   g_is64;

__device__ __forceinline__ float silu_f(float x) {
    return x / (1.0f + __expf(-x));
}
__device__ __forceinline__ float4 silu4(float4 v) {
    v.x = silu_f(v.x); v.y = silu_f(v.y); v.z = silu_f(v.z); v.w = silu_f(v.w);
    return v;
}

// Copy a 128x128 fp32 weight matrix (row-major, [k][n]) into shared.
__device__ __forceinline__ void load_w(float* ws, const float* __restrict__ W, int tid) {
    const float4* W4 = (const float4*)W;
    float4* s4 = (float4*)ws;
    #pragma unroll
    for (int i = 0; i < 16; i++) s4[tid + i * 256] = W4[tid + i * 256];
}

// acc[i][j] += ts[ty*8+i][k] * ws[k][tx*8+j], K = 128.
// ts rows padded to PAD floats. a-loads broadcast within warp; b-loads are LDS.128.
__device__ __forceinline__ void tile_gemm(const float* __restrict__ ts,
                                          const float* __restrict__ ws,
                                          float acc[8][8], int tx, int ty) {
    const float* tr = ts + ty * 8 * PAD;
    const float* wc = ws + tx * 8;
    #pragma unroll 2
    for (int k0 = 0; k0 < DD; k0 += 4) {
        float4 av[8];
        #pragma unroll
        for (int i = 0; i < 8; i++)
            av[i] = *(const float4*)(tr + i * PAD + k0);
        #pragma unroll
        for (int kk = 0; kk < 4; kk++) {
            const float* wrow = wc + (k0 + kk) * DD;
            float4 b0 = *(const float4*)(wrow);
            float4 b1 = *(const float4*)(wrow + 4);
            #pragma unroll
            for (int i = 0; i < 8; i++) {
                float a = (kk == 0) ? av[i].x : (kk == 1) ? av[i].y
                        : (kk == 2) ? av[i].z : av[i].w;
                acc[i][0] = fmaf(a, b0.x, acc[i][0]);
                acc[i][1] = fmaf(a, b0.y, acc[i][1]);
                acc[i][2] = fmaf(a, b0.z, acc[i][2]);
                acc[i][3] = fmaf(a, b0.w, acc[i][3]);
                acc[i][4] = fmaf(a, b1.x, acc[i][4]);
                acc[i][5] = fmaf(a, b1.y, acc[i][5]);
                acc[i][6] = fmaf(a, b1.z, acc[i][6]);
                acc[i][7] = fmaf(a, b1.w, acc[i][7]);
            }
        }
    }
}

// Zero the aggregation buffer + detect edge-index width (int64 vs int32).
__global__ void zero_detect_kernel(const void* __restrict__ eidx) {
    size_t i = (size_t)blockIdx.x * blockDim.x + threadIdx.x;
    size_t n4 = (size_t)MAXN * DD / 4;
    if (i < n4) ((float4*)g_agg)[i] = make_float4(0.f, 0.f, 0.f, 0.f);
    if (blockIdx.x == 0 && threadIdx.x == 0) {
        // int64 values < 2^32 -> every high word is 0. For int32, odd words are
        // random indices in [0,50000): P(all 64 zero) ~ 0. Deterministic per input.
        const unsigned* p = (const unsigned*)eidx;
        int is64 = 1;
        for (int k = 0; k < 64; k++)
            if (p[2 * k + 1] != 0u) { is64 = 0; break; }
        g_is64 = is64;
    }
}

// Precompute A = h@We1_top, B = h@We1_bot, C = h@Wn1_top + bn1.
__global__ void __launch_bounds__(NTHR, 1)
pre_kernel(const float* __restrict__ h, const float* __restrict__ We1,
           const float* __restrict__ Wn1, const float* __restrict__ bn1, int Nn) {
    extern __shared__ float sm[];
    float* ts = sm;                  // TM x PAD
    float* ws = sm + TM * PAD;       // 128 x 128
    int tid = threadIdx.x;
    int nb = blockIdx.x * TM;

    int el = tid >> 1, half = tid & 1;
    int node = nb + el;
    float* td = ts + el * PAD + half * 64;
    if (node < Nn) {
        const float4* h4 = (const float4*)(h + (size_t)node * DD + half * 64);
        #pragma unroll
        for (int i = 0; i < 16; i++) ((float4*)td)[i] = h4[i];
    } else {
        float4 z = make_float4(0.f, 0.f, 0.f, 0.f);
        #pragma unroll
        for (int i = 0; i < 16; i++) ((float4*)td)[i] = z;
    }

    int tx = tid & 15, ty = tid >> 4;
    for (int ph = 0; ph < 3; ph++) {
        const float* W = (ph == 0) ? We1 : (ph == 1) ? (We1 + DD * DD) : Wn1;
        __syncthreads();             // ts ready (ph 0) / prior ws reads done (ph>0)
        load_w(ws, W, tid);
        __syncthreads();

        float acc[8][8];
        #pragma unroll
        for (int i = 0; i < 8; i++)
            #pragma unroll
            for (int j = 0; j < 8; j++) acc[i][j] = 0.f;
        tile_gemm(ts, ws, acc, tx, ty);

        float* out = (ph == 0) ? g_A : (ph == 1) ? g_B : g_C;
        float4 b0 = make_float4(0.f, 0.f, 0.f, 0.f), b1 = b0;
        if (ph == 2) {
            b0 = __ldg((const float4*)(bn1 + tx * 8));
            b1 = __ldg((const float4*)(bn1 + tx * 8) + 1);
        }
        #pragma unroll
        for (int i = 0; i < 8; i++) {
            int nd = nb + ty * 8 + i;
            if (nd < Nn) {
                float4 v0 = make_float4(acc[i][0] + b0.x, acc[i][1] + b0.y,
                                        acc[i][2] + b0.z, acc[i][3] + b0.w);
                float4 v1 = make_float4(acc[i][4] + b1.x, acc[i][5] + b1.y,
                                        acc[i][6] + b1.z, acc[i][7] + b1.w);
                float* op = out + (size_t)nd * DD + tx * 8;
                *(float4*)op = v0;
                *(float4*)(op + 4) = v1;
            }
        }
    }
}

// Edge pipeline: gather A[row]+B[col]+be1 -> silu -> GEMM with We2 -> silu ->
// write mij + scatter-add into g_agg.
__global__ void __launch_bounds__(NTHR, 1)
edge_kernel(const void* __restrict__ eidx, const float* __restrict__ be1,
            const float* __restrict__ We2, const float* __restrict__ be2,
            float* __restrict__ mij, int Ee) {
    extern __shared__ float sm[];
    float* ts = sm;
    float* ws = sm + TM * PAD;
    __shared__ int rsh[TM];
    int tid = threadIdx.x;
    int eb = blockIdx.x * TM;

    load_w(ws, We2, tid);

    int el = tid >> 1, half = tid & 1;
    int e = eb + el;
    int ec = (e < Ee) ? e : (Ee - 1);
    int r, c;
    if (g_is64) {
        const long long* p = (const long long*)eidx;
        r = (int)p[ec];
        c = (int)p[(size_t)Ee + ec];
    } else {
        const int* p = (const int*)eidx;
        r = p[ec];
        c = p[Ee + ec];
    }
    if (half == 0) rsh[el] = r;

    const float4* A4 = (const float4*)(g_A + (size_t)r * DD + half * 64);
    const float4* B4 = (const float4*)(g_B + (size_t)c * DD + half * 64);
    const float4* bb4 = (const float4*)(be1 + half * 64);
    float* td = ts + el * PAD + half * 64;
    #pragma unroll
    for (int i = 0; i < 16; i++) {
        float4 a = A4[i], b = B4[i], bb = bb4[i];
        float4 v = make_float4(silu_f(a.x + b.x + bb.x), silu_f(a.y + b.y + bb.y),
                               silu_f(a.z + b.z + bb.z), silu_f(a.w + b.w + bb.w));
        ((float4*)td)[i] = v;
    }
    __syncthreads();

    int tx = tid & 15, ty = tid >> 4;
    float acc[8][8];
    #pragma unroll
    for (int i = 0; i < 8; i++)
        #pragma unroll
        for (int j = 0; j < 8; j++) acc[i][j] = 0.f;
    tile_gemm(ts, ws, acc, tx, ty);

    float4 c0 = __ldg((const float4*)(be2 + tx * 8));
    float4 c1 = __ldg((const float4*)(be2 + tx * 8) + 1);
    #pragma unroll
    for (int i = 0; i < 8; i++) {
        int ee = eb + ty * 8 + i;
        if (ee < Ee) {
            int rr = rsh[ty * 8 + i];
            float4 v0 = silu4(make_float4(acc[i][0] + c0.x, acc[i][1] + c0.y,
                                          acc[i][2] + c0.z, acc[i][3] + c0.w));
            float4 v1 = silu4(make_float4(acc[i][4] + c1.x, acc[i][5] + c1.y,
                                          acc[i][6] + c1.z, acc[i][7] + c1.w));
            float* mp = mij + (size_t)ee * DD + tx * 8;
            *(float4*)mp = v0;
            *(float4*)(mp + 4) = v1;
            float* ap = g_agg + (size_t)rr * DD + tx * 8;
            atomicAdd(ap + 0, v0.x); atomicAdd(ap + 1, v0.y);
            atomicAdd(ap + 2, v0.z); atomicAdd(ap + 3, v0.w);
            atomicAdd(ap + 4, v1.x); atomicAdd(ap + 5, v1.y);
            atomicAdd(ap + 6, v1.z); atomicAdd(ap + 7, v1.w);
        }
    }
}

// Node pipeline: u = silu(C + (agg/100) @ Wn1_bot); h_out = h + u @ Wn2 + bn2.
__global__ void __launch_bounds__(NTHR, 1)
node_kernel(const float* __restrict__ h, const float* __restrict__ Wn1,
            const float* __restrict__ Wn2, const float* __restrict__ bn2,
            float* __restrict__ hout, int Nn) {
    extern __shared__ float sm[];
    float* ts = sm;
    float* ws = sm + TM * PAD;
    int tid = threadIdx.x;
    int nb = blockIdx.x * TM;

    int el = tid >> 1, half = tid & 1;
    int node = nb + el;
    float* td = ts + el * PAD + half * 64;
    const float inv = 0.01f;
    if (node < Nn) {
        const float4* g4 = (const float4*)(g_agg + (size_t)node * DD + half * 64);
        #pragma unroll
        for (int i = 0; i < 16; i++) {
            float4 v = g4[i];
            v.x *= inv; v.y *= inv; v.z *= inv; v.w *= inv;
            ((float4*)td)[i] = v;
        }
    } else {
        float4 z = make_float4(0.f, 0.f, 0.f, 0.f);
        #pragma unroll
        for (int i = 0; i < 16; i++) ((float4*)td)[i] = z;
    }
    load_w(ws, Wn1 + DD * DD, tid);   // Wn1_bot
    __syncthreads();

    int tx = tid & 15, ty = tid >> 4;
    float acc[8][8];
    #pragma unroll
    for (int i = 0; i < 8; i++)
        #pragma unroll
        for (int j = 0; j < 8; j++) acc[i][j] = 0.f;
    tile_gemm(ts, ws, acc, tx, ty);
    __syncthreads();   // all reads of ts/ws done

    // u = silu(acc + C) back into ts (each thread writes its own cells)
    #pragma unroll
    for (int i = 0; i < 8; i++) {
        int nd = nb + ty * 8 + i;
        float4 u0 = make_float4(0.f, 0.f, 0.f, 0.f), u1 = u0;
        if (nd < Nn) {
            const float4* Cp = (const float4*)(g_C + (size_t)nd * DD + tx * 8);
            float4 cc0 = Cp[0], cc1 = Cp[1];
            u0 = silu4(make_float4(acc[i][0] + cc0.x, acc[i][1] + cc0.y,
                                   acc[i][2] + cc0.z, acc[i][3] + cc0.w));
            u1 = silu4(make_float4(acc[i][4] + cc1.x, acc[i][5] + cc1.y,
                                   acc[i][6] + cc1.z, acc[i][7] + cc1.w));
        }
        float* tp = ts + (ty * 8 + i) * PAD + tx * 8;
        *(float4*)tp = u0;
        *(float4*)(tp + 4) = u1;
    }
    load_w(ws, Wn2, tid);
    __syncthreads();

    float acc2[8][8];
    #pragma unroll
    for (int i = 0; i < 8; i++)
        #pragma unroll
        for (int j = 0; j < 8; j++) acc2[i][j] = 0.f;
    tile_gemm(ts, ws, acc2, tx, ty);

    float4 b0 = __ldg((const float4*)(bn2 + tx * 8));
    float4 b1 = __ldg((const float4*)(bn2 + tx * 8) + 1);
    #pragma unroll
    for (int i = 0; i < 8; i++) {
        int nd = nb + ty * 8 + i;
        if (nd < Nn) {
            const float4* hp = (const float4*)(h + (size_t)nd * DD + tx * 8);
            float4 h0 = hp[0], h1 = hp[1];
            float4 v0 = make_float4(h0.x + acc2[i][0] + b0.x, h0.y + acc2[i][1] + b0.y,
                                    h0.z + acc2[i][2] + b0.z, h0.w + acc2[i][3] + b0.w);
            float4 v1 = make_float4(h1.x + acc2[i][4] + b1.x, h1.y + acc2[i][5] + b1.y,
                                    h1.z + acc2[i][6] + b1.z, h1.w + acc2[i][7] + b1.w);
            float* op = hout + (size_t)nd * DD + tx * 8;
            *(float4*)op = v0;
            *(float4*)(op + 4) = v1;
        }
    }
}

extern "C" void kernel_launch(void* const* d_in, const int* in_sizes, int n_in,
                              void* d_out, int out_size) {
    const float* h   = (const float*)d_in[0];
    const void*  eix = d_in[1];
    const float* We1 = (const float*)d_in[2];
    const float* be1 = (const float*)d_in[3];
    const float* We2 = (const float*)d_in[4];
    const float* be2 = (const float*)d_in[5];
    const float* Wn1 = (const float*)d_in[6];
    const float* bn1 = (const float*)d_in[7];
    const float* Wn2 = (const float*)d_in[8];
    const float* bn2 = (const float*)d_in[9];

    int Nn = in_sizes[0] / DD;     // 50000
    int Ee = in_sizes[1] / 2;      // 800000

    float* hout = (float*)d_out;
    float* mij  = (float*)d_out + (size_t)Nn * DD;

    size_t smem = (size_t)(TM * PAD + DD * DD) * sizeof(float);  // ~130 KB
    cudaFuncSetAttribute(pre_kernel,  cudaFuncAttributeMaxDynamicSharedMemorySize, (int)smem);
    cudaFuncSetAttribute(edge_kernel, cudaFuncAttributeMaxDynamicSharedMemorySize, (int)smem);
    cudaFuncSetAttribute(node_kernel, cudaFuncAttributeMaxDynamicSharedMemorySize, (int)smem);

    int gz = (MAXN * DD / 4 + NTHR - 1) / NTHR;
    zero_detect_kernel<<<gz, NTHR>>>(eix);

    int gn = (Nn + TM - 1) / TM;
    pre_kernel<<<gn, NTHR, smem>>>(h, We1, Wn1, bn1, Nn);

    int ge = (Ee + TM - 1) / TM;
    edge_kernel<<<ge, NTHR, smem>>>(eix, be1, We2, be2, mij, Ee);

    node_kernel<<<gn, NTHR, smem>>>(h, Wn1, Wn2, bn2, hout, Nn);
}

// round 3
// speedup vs baseline: 1.8581x; 1.8581x over previous
#include <cuda_runtime.h>
#include <cstdint>
#include <cstddef>

// GCL (EGNN-style graph conv layer), factorized + tf32 mma.sync (compute_100-safe):
//   A = h @ We1_top, B = h @ We1_bot, C = h @ Wn1_top + bn1   (pre, MMA)
//   t_e   = silu(A[row_e] + B[col_e] + be1)
//   mij_e = silu(t_e @ We2 + be2)        <-- persistent MMA kernel + scatter
//   agg_n = (sum_{e: row==n} mij_e)/100
//   h_out = h + silu(C + agg @ Wn1_bot) @ Wn2 + bn2            (node, MMA x2)
// Output: [h_out (N*D) | mij (E*D)] fp32.

#define DD    128
#define PAD   132     // ts row pitch (floats): A-frag banks 4g+tg -> conflict-free
#define PADW  136     // ws row pitch (floats): B-frag banks 8tg+g -> conflict-free
#define TM    128
#define NTHR  256
#define MAXN  50048
#define EGRID 148

__device__ float g_A[(size_t)MAXN * DD];
__device__ float g_B[(size_t)MAXN * DD];
__device__ float g_C[(size_t)MAXN * DD];
__device__ float g_agg[(size_t)MAXN * DD];
__device__ int   g_is64;

__device__ __forceinline__ float silu_f(float x) { return x / (1.0f + __expf(-x)); }

__device__ __forceinline__ float to_tf32(float x) {
    uint32_t u;
    asm("cvt.rna.tf32.f32 %0, %1;" : "=r"(u) : "f"(x));
    return __uint_as_float(u);
}

__device__ __forceinline__ void mma_tf32(float c[4], uint32_t a0, uint32_t a1,
                                         uint32_t a2, uint32_t a3,
                                         uint32_t b0, uint32_t b1) {
    asm("mma.sync.aligned.m16n8k8.row.col.f32.tf32.tf32.f32 "
        "{%0,%1,%2,%3}, {%4,%5,%6,%7}, {%8,%9}, {%0,%1,%2,%3};"
        : "+f"(c[0]), "+f"(c[1]), "+f"(c[2]), "+f"(c[3])
        : "r"(a0), "r"(a1), "r"(a2), "r"(a3), "r"(b0), "r"(b1));
}

// Load 128x128 row-major W into ws[k*PADW + n], tf32-rounded. Coalesced float4.
__device__ __forceinline__ void load_w(float* ws, const float* __restrict__ W, int tid) {
    #pragma unroll
    for (int i = 0; i < 16; i++) {
        int idx = tid + i * NTHR;          // float4 index, 4096 total
        int k = idx >> 5;                  // 32 float4 per 128-float row
        int n4 = (idx & 31) << 2;
        float4 v = __ldg((const float4*)W + idx);
        v.x = to_tf32(v.x); v.y = to_tf32(v.y);
        v.z = to_tf32(v.z); v.w = to_tf32(v.w);
        *(float4*)(ws + k * PADW + n4) = v;
    }
}

// 128x128x128 warp-tiled MMA: acc += ts[128][k128] @ ws[k][n].
// Warp grid 2(M)x4(N): warp = M 64 x N 32. m16n8k8 tf32 fragments.
__device__ __forceinline__ void warp_gemm(const float* __restrict__ ts,
                                          const float* __restrict__ ws,
                                          float acc[4][4][4],
                                          int wm, int wn, int g, int tg) {
    const float* ta = ts + (wm * 64 + g) * PAD + tg;
    const float* wb = ws + tg * PADW + wn * 32 + g;
    #pragma unroll
    for (int ks = 0; ks < 16; ks++) {
        int kb = ks * 8;
        uint32_t a[4][4];
        #pragma unroll
        for (int mt = 0; mt < 4; mt++) {
            const float* p = ta + mt * 16 * PAD + kb;
            a[mt][0] = __float_as_uint(p[0]);
            a[mt][1] = __float_as_uint(p[8 * PAD]);
            a[mt][2] = __float_as_uint(p[4]);
            a[mt][3] = __float_as_uint(p[8 * PAD + 4]);
        }
        #pragma unroll
        for (int nt = 0; nt < 4; nt++) {
            const float* q = wb + kb * PADW + nt * 8;
            uint32_t b0 = __float_as_uint(q[0]);
            uint32_t b1 = __float_as_uint(q[4 * PADW]);
            #pragma unroll
            for (int mt = 0; mt < 4; mt++)
                mma_tf32(acc[mt][nt], a[mt][0], a[mt][1], a[mt][2], a[mt][3], b0, b1);
        }
    }
}

// ============================ setup ============================

__global__ void zero_detect_kernel(const void* __restrict__ eidx) {
    size_t i = (size_t)blockIdx.x * blockDim.x + threadIdx.x;
    size_t n4 = (size_t)MAXN * DD / 4;
    if (i < n4) ((float4*)g_agg)[i] = make_float4(0.f, 0.f, 0.f, 0.f);
    if (blockIdx.x == 0 && threadIdx.x == 0) {
        // int64 indices < 2^32 -> all high words zero; int32 -> odd words are
        // random node ids, essentially never all zero. Deterministic per input.
        const unsigned* p = (const unsigned*)eidx;
        int is64 = 1;
        for (int k = 0; k < 64; k++)
            if (p[2 * k + 1] != 0u) { is64 = 0; break; }
        g_is64 = is64;
    }
}

// ============================ pre: A, B, C ============================

__global__ void __launch_bounds__(NTHR, 1)
pre_kernel(const float* __restrict__ h, const float* __restrict__ We1,
           const float* __restrict__ Wn1, const float* __restrict__ bn1, int Nn) {
    extern __shared__ float sm[];
    float* ts = sm;
    float* ws = sm + TM * PAD;
    int tid = threadIdx.x, lane = tid & 31, wid = tid >> 5;
    int wm = wid >> 2, wn = wid & 3, g = lane >> 2, tg = lane & 3;
    int nb = blockIdx.x * TM;
    int el = tid >> 1, half = tid & 1;

    {
        int node = nb + el;
        float* td = ts + el * PAD + half * 64;
        if (node < Nn) {
            const float4* h4 = (const float4*)(h + (size_t)node * DD + half * 64);
            #pragma unroll
            for (int i = 0; i < 16; i++) {
                float4 v = h4[i];
                v.x = to_tf32(v.x); v.y = to_tf32(v.y);
                v.z = to_tf32(v.z); v.w = to_tf32(v.w);
                ((float4*)td)[i] = v;
            }
        } else {
            float4 z = make_float4(0.f, 0.f, 0.f, 0.f);
            #pragma unroll
            for (int i = 0; i < 16; i++) ((float4*)td)[i] = z;
        }
    }

    for (int ph = 0; ph < 3; ph++) {
        const float* W = (ph == 0) ? We1 : (ph == 1) ? (We1 + DD * DD) : Wn1;
        __syncthreads();                 // ts ready / previous ws reads done
        load_w(ws, W, tid);
        __syncthreads();

        float acc[4][4][4] = {};
        warp_gemm(ts, ws, acc, wm, wn, g, tg);

        float* out = (ph == 0) ? g_A : (ph == 1) ? g_B : g_C;
        #pragma unroll
        for (int mt = 0; mt < 4; mt++) {
            int r0 = wm * 64 + mt * 16 + g;
            int n0 = nb + r0, n1 = n0 + 8;
            #pragma unroll
            for (int nt = 0; nt < 4; nt++) {
                int cb = wn * 32 + nt * 8 + tg * 2;
                float2 bb = make_float2(0.f, 0.f);
                if (ph == 2) bb = *(const float2*)(bn1 + cb);
                if (n0 < Nn)
                    *(float2*)(out + (size_t)n0 * DD + cb) =
                        make_float2(acc[mt][nt][0] + bb.x, acc[mt][nt][1] + bb.y);
                if (n1 < Nn)
                    *(float2*)(out + (size_t)n1 * DD + cb) =
                        make_float2(acc[mt][nt][2] + bb.x, acc[mt][nt][3] + bb.y);
            }
        }
    }
}

// ============================ edge (persistent) ============================

__device__ __forceinline__ void pf_load(int t, int Ee, int is64,
                                        const void* __restrict__ eidx,
                                        const float* __restrict__ sbe1,
                                        int el, int half,
                                        float4 pf[16], int& pr) {
    int e = t * TM + el;
    int ec = (e < Ee) ? e : (Ee - 1);
    int r, c;
    if (is64) {
        const long long* p = (const long long*)eidx;
        r = (int)p[ec];
        c = (int)p[(size_t)Ee + ec];
    } else {
        const int* p = (const int*)eidx;
        r = p[ec];
        c = p[Ee + ec];
    }
    pr = r;
    const float4* Ar = (const float4*)(g_A + (size_t)r * DD + half * 64);
    const float4* Br = (const float4*)(g_B + (size_t)c * DD + half * 64);
    #pragma unroll
    for (int i = 0; i < 16; i++) {
        float4 a = Ar[i], b = Br[i];
        int kc = half * 64 + i * 4;
        float4 v;
        v.x = to_tf32(silu_f(a.x + b.x + sbe1[kc + 0]));
        v.y = to_tf32(silu_f(a.y + b.y + sbe1[kc + 1]));
        v.z = to_tf32(silu_f(a.z + b.z + sbe1[kc + 2]));
        v.w = to_tf32(silu_f(a.w + b.w + sbe1[kc + 3]));
        pf[i] = v;
    }
}

__global__ void __launch_bounds__(NTHR, 1)
edge_kernel(const void* __restrict__ eidx, const float* __restrict__ be1,
            const float* __restrict__ We2, const float* __restrict__ be2,
            float* __restrict__ mij, int Ee) {
    extern __shared__ float sm[];
    float* ts = sm;
    float* ws = sm + TM * PAD;
    __shared__ int rsh[TM];
    __shared__ float sbe1[DD], sbe2[DD];

    int tid = threadIdx.x, lane = tid & 31, wid = tid >> 5;
    int wm = wid >> 2, wn = wid & 3, g = lane >> 2, tg = lane & 3;
    int el = tid >> 1, half = tid & 1;

    if (tid < DD) { sbe1[tid] = be1[tid]; sbe2[tid] = be2[tid]; }
    load_w(ws, We2, tid);
    int is64 = g_is64;
    __syncthreads();                       // sbe1 visible for pf_load

    int ntiles = (Ee + TM - 1) >> 7;
    int t = blockIdx.x;
    float4 pf[16];
    int pr = 0;
    if (t < ntiles) {
        pf_load(t, Ee, is64, eidx, sbe1, el, half, pf, pr);
        float* td = ts + el * PAD + half * 64;
        #pragma unroll
        for (int i = 0; i < 16; i++) ((float4*)td)[i] = pf[i];
        if (!half) rsh[el] = pr;
    }
    __syncthreads();

    for (; t < ntiles; t += gridDim.x) {
        float acc[4][4][4] = {};
        warp_gemm(ts, ws, acc, wm, wn, g, tg);

        int tn = t + gridDim.x;
        if (tn < ntiles)                   // issue next gather early: latency
            pf_load(tn, Ee, is64, eidx, sbe1, el, half, pf, pr);  // hides under epilogue

        // epilogue: mij = silu(acc + be2); scatter-add into g_agg
        #pragma unroll
        for (int mt = 0; mt < 4; mt++) {
            int r0 = wm * 64 + mt * 16 + g;
            int e0 = t * TM + r0, e1 = e0 + 8;
            int rr0 = rsh[r0], rr1 = rsh[r0 + 8];
            float* m0 = mij + (size_t)e0 * DD;
            float* m1 = mij + (size_t)e1 * DD;
            float* a0p = g_agg + (size_t)rr0 * DD;
            float* a1p = g_agg + (size_t)rr1 * DD;
            bool ok0 = e0 < Ee, ok1 = e1 < Ee;
            #pragma unroll
            for (int nt = 0; nt < 4; nt++) {
                int cb = wn * 32 + nt * 8 + tg * 2;
                float2 u0 = make_float2(silu_f(acc[mt][nt][0] + sbe2[cb]),
                                        silu_f(acc[mt][nt][1] + sbe2[cb + 1]));
                float2 u1 = make_float2(silu_f(acc[mt][nt][2] + sbe2[cb]),
                                        silu_f(acc[mt][nt][3] + sbe2[cb + 1]));
                if (ok0) { *(float2*)(m0 + cb) = u0; atomicAdd((float2*)(a0p + cb), u0); }
                if (ok1) { *(float2*)(m1 + cb) = u1; atomicAdd((float2*)(a1p + cb), u1); }
            }
        }
        __syncthreads();                   // everyone done reading ts/rsh
        if (tn < ntiles) {
            float* td = ts + el * PAD + half * 64;
            #pragma unroll
            for (int i = 0; i < 16; i++) ((float4*)td)[i] = pf[i];
            if (!half) rsh[el] = pr;
        }
        __syncthreads();                   // ts/rsh ready for next MMA
    }
}

// ============================ node ============================

__global__ void __launch_bounds__(NTHR, 1)
node_kernel(const float* __restrict__ h, const float* __restrict__ Wn1,
            const float* __restrict__ Wn2, const float* __restrict__ bn2,
            float* __restrict__ hout, int Nn) {
    extern __shared__ float sm[];
    float* ts = sm;
    float* ws = sm + TM * PAD;
    int tid = threadIdx.x, lane = tid & 31, wid = tid >> 5;
    int wm = wid >> 2, wn = wid & 3, g = lane >> 2, tg = lane & 3;
    int nb = blockIdx.x * TM;
    int el = tid >> 1, half = tid & 1;

    {
        int node = nb + el;
        float* td = ts + el * PAD + half * 64;
        if (node < Nn) {
            const float4* g4 = (const float4*)(g_agg + (size_t)node * DD + half * 64);
            #pragma unroll
            for (int i = 0; i < 16; i++) {
                float4 v = g4[i];
                v.x = to_tf32(v.x * 0.01f); v.y = to_tf32(v.y * 0.01f);
                v.z = to_tf32(v.z * 0.01f); v.w = to_tf32(v.w * 0.01f);
                ((float4*)td)[i] = v;
            }
        } else {
            float4 z = make_float4(0.f, 0.f, 0.f, 0.f);
            #pragma unroll
            for (int i = 0; i < 16; i++) ((float4*)td)[i] = z;
        }
    }
    load_w(ws, Wn1 + DD * DD, tid);        // Wn1_bot
    __syncthreads();

    float acc[4][4][4] = {};
    warp_gemm(ts, ws, acc, wm, wn, g, tg);
    __syncthreads();                       // all reads of ts/ws done

    // u = silu(acc + C) -> ts (tf32-rounded), load Wn2
    #pragma unroll
    for (int mt = 0; mt < 4; mt++) {
        int r0 = wm * 64 + mt * 16 + g;
        int n0 = nb + r0, n1 = n0 + 8;
        #pragma unroll
        for (int nt = 0; nt < 4; nt++) {
            int cb = wn * 32 + nt * 8 + tg * 2;
            float2 u0 = make_float2(0.f, 0.f), u1 = u0;
            if (n0 < Nn) {
                float2 c0 = *(const float2*)(g_C + (size_t)n0 * DD + cb);
                u0 = make_float2(to_tf32(silu_f(acc[mt][nt][0] + c0.x)),
                                 to_tf32(silu_f(acc[mt][nt][1] + c0.y)));
            }
            if (n1 < Nn) {
                float2 c1 = *(const float2*)(g_C + (size_t)n1 * DD + cb);
                u1 = make_float2(to_tf32(silu_f(acc[mt][nt][2] + c1.x)),
                                 to_tf32(silu_f(acc[mt][nt][3] + c1.y)));
            }
            *(float2*)(ts + r0 * PAD + cb) = u0;
            *(float2*)(ts + (r0 + 8) * PAD + cb) = u1;
        }
    }
    load_w(ws, Wn2, tid);
    __syncthreads();

    float acc2[4][4][4] = {};
    warp_gemm(ts, ws, acc2, wm, wn, g, tg);

    #pragma unroll
    for (int mt = 0; mt < 4; mt++) {
        int r0 = wm * 64 + mt * 16 + g;
        int n0 = nb + r0, n1 = n0 + 8;
        #pragma unroll
        for (int nt = 0; nt < 4; nt++) {
            int cb = wn * 32 + nt * 8 + tg * 2;
            float2 bb = *(const float2*)(bn2 + cb);
            if (n0 < Nn) {
                float2 hv = *(const float2*)(h + (size_t)n0 * DD + cb);
                *(float2*)(hout + (size_t)n0 * DD + cb) =
                    make_float2(hv.x + acc2[mt][nt][0] + bb.x,
                                hv.y + acc2[mt][nt][1] + bb.y);
            }
            if (n1 < Nn) {
                float2 hv = *(const float2*)(h + (size_t)n1 * DD + cb);
                *(float2*)(hout + (size_t)n1 * DD + cb) =
                    make_float2(hv.x + acc2[mt][nt][2] + bb.x,
                                hv.y + acc2[mt][nt][3] + bb.y);
            }
        }
    }
}

// ============================ launcher ============================

extern "C" void kernel_launch(void* const* d_in, const int* in_sizes, int n_in,
                              void* d_out, int out_size) {
    const float* h   = (const float*)d_in[0];
    const void*  eix = d_in[1];
    const float* We1 = (const float*)d_in[2];
    const float* be1 = (const float*)d_in[3];
    const float* We2 = (const float*)d_in[4];
    const float* be2 = (const float*)d_in[5];
    const float* Wn1 = (const float*)d_in[6];
    const float* bn1 = (const float*)d_in[7];
    const float* Wn2 = (const float*)d_in[8];
    const float* bn2 = (const float*)d_in[9];

    int Nn = in_sizes[0] / DD;     // 50000
    int Ee = in_sizes[1] / 2;      // 800000

    float* hout = (float*)d_out;
    float* mij  = (float*)d_out + (size_t)Nn * DD;

    size_t smem = (size_t)(TM * PAD + DD * PADW) * sizeof(float);  // 137,216 B
    cudaFuncSetAttribute(pre_kernel,  cudaFuncAttributeMaxDynamicSharedMemorySize, (int)smem);
    cudaFuncSetAttribute(edge_kernel, cudaFuncAttributeMaxDynamicSharedMemorySize, (int)smem);
    cudaFuncSetAttribute(node_kernel, cudaFuncAttributeMaxDynamicSharedMemorySize, (int)smem);

    int gz = (MAXN * DD / 4 + NTHR - 1) / NTHR;
    zero_detect_kernel<<<gz, NTHR>>>(eix);

    int gn = (Nn + TM - 1) / TM;
    pre_kernel<<<gn, NTHR, smem>>>(h, We1, Wn1, bn1, Nn);

    edge_kernel<<<EGRID, NTHR, smem>>>(eix, be1, We2, be2, mij, Ee);

    node_kernel<<<gn, NTHR, smem>>>(h, Wn1, Wn2, bn2, hout, Nn);
}